// round 1
// baseline (speedup 1.0000x reference)
#include <cuda_runtime.h>
#include <cuda_bf16.h>
#include <cstdint>

#define B_ROWS 2048
#define D_DIM  512
#define N_COLS 100000
#define NPAD   100096           // 782 * 128
#define NW     (NPAD / 32)      // 3128 mask words per row
#define F_LEN  64
#define BM 128
#define BN 128
#define BK 32
#define KT (D_DIM / BK)         // 16 k-stages

// ---------------- device scratch (static globals; no allocation) ----------------
__device__ __nv_bfloat16 g_rhs_bf16[(size_t)D_DIM * NPAD];   // ~102.5 MB
__device__ __nv_bfloat16 g_q_bf16[B_ROWS * D_DIM];           // 2 MB
__device__ float         g_targets[B_ROWS];
__device__ int           g_counts[B_ROWS];
__device__ unsigned      g_mask[(size_t)B_ROWS * NW];        // ~25.6 MB bitmap
__device__ int           g_is64;

// ---------------- index dtype detection (jax may silently downcast int64->int32) ----
__global__ void k_detect(const unsigned* __restrict__ qb) {
    __shared__ unsigned s;
    if (threadIdx.x == 0) s = 0;
    __syncthreads();
    unsigned a = 0;
    for (int i = threadIdx.x; i < 3 * B_ROWS; i += blockDim.x) a |= qb[2 * i + 1];
    atomicOr(&s, a);
    __syncthreads();
    if (threadIdx.x == 0) g_is64 = (s == 0) ? 1 : 0;
}

__device__ __forceinline__ int load_idx(const void* p, int i) {
    if (g_is64) return (int)((const long long*)p)[i];
    return ((const int*)p)[i];
}

// ---------------- prep: rhs fp32 -> bf16 (padded, pad cols = 0) ----------------
__global__ void k_prep_rhs(const float* __restrict__ rhs) {
    int idx = blockIdx.x * 256 + threadIdx.x;     // exactly D_DIM*NPAD threads
    int d = idx / NPAD, n = idx - d * NPAD;
    float v = (n < N_COLS) ? rhs[(size_t)d * N_COLS + n] : 0.f;
    g_rhs_bf16[idx] = __float2bfloat16(v);
}

// ---------------- prep: q fp32 -> bf16, zero counts ----------------
__global__ void k_prep_q(const float* __restrict__ q) {
    int idx = blockIdx.x * 256 + threadIdx.x;     // B_ROWS*D_DIM threads
    g_q_bf16[idx] = __float2bfloat16(q[idx]);
    if (idx < B_ROWS) g_counts[idx] = 0;
}

// ---------------- mask bitmap: zero then scatter ----------------
__global__ void k_mask_zero() {
    int idx = blockIdx.x * 256 + threadIdx.x;     // B_ROWS*NW threads
    g_mask[idx] = 0u;
}

__global__ void k_mask_fill(const void* __restrict__ queries,
                            const void* __restrict__ filt) {
    int t = blockIdx.x * blockDim.x + threadIdx.x;
    if (t >= B_ROWS * 65) return;
    int b = t / 65, j = t - b * 65;
    int idx = (j < F_LEN) ? load_idx(filt, b * F_LEN + j)
                          : load_idx(queries, b * 3 + 2);
    atomicOr(&g_mask[(size_t)b * NW + (idx >> 5)], 1u << (idx & 31));
}

// ---------------- exact fp32 targets: one warp per row ----------------
__global__ void k_targets(const float* __restrict__ q, const float* __restrict__ rhs,
                          const void* __restrict__ queries) {
    int warp = threadIdx.x >> 5, lane = threadIdx.x & 31;
    int b = blockIdx.x * 8 + warp;
    int n = load_idx(queries, b * 3 + 2);
    float s = 0.f;
    for (int d = lane; d < D_DIM; d += 32)
        s += q[b * D_DIM + d] * rhs[(size_t)d * N_COLS + n];
#pragma unroll
    for (int o = 16; o > 0; o >>= 1) s += __shfl_xor_sync(0xffffffffu, s, o);
    if (lane == 0) g_targets[b] = s;
}

// ---------------- main: bf16 MMA GEMM with counting epilogue ----------------
__global__ void __launch_bounds__(256, 2) k_gemm() {
    __shared__ __nv_bfloat16 sA[2][BM][BK + 8];   // row stride 40 (80B, conflict-free ldmatrix)
    __shared__ __nv_bfloat16 sB[2][BK][BN + 8];   // row stride 136 (272B, conflict-free)

    const int tid = threadIdx.x, lane = tid & 31, warp = tid >> 5;
    const int wm = warp >> 1, wn = warp & 1;      // 4x2 warp grid, warp tile 32x64
    const int m0 = blockIdx.x * BM, n0 = blockIdx.y * BN;

    float acc[2][8][4];
#pragma unroll
    for (int mi = 0; mi < 2; mi++)
#pragma unroll
        for (int ni = 0; ni < 8; ni++)
#pragma unroll
            for (int e = 0; e < 4; e++) acc[mi][ni][e] = 0.f;

    auto load_stage = [&](int kt, int buf) {
        int k0 = kt * BK;
#pragma unroll
        for (int i = 0; i < 2; i++) {            // A tile: 128x32 bf16, 16B chunks
            int c = tid + i * 256;
            int r = c >> 2, cc = c & 3;
            uint32_t d = (uint32_t)__cvta_generic_to_shared(&sA[buf][r][cc * 8]);
            const __nv_bfloat16* g = &g_q_bf16[(m0 + r) * D_DIM + k0 + cc * 8];
            asm volatile("cp.async.cg.shared.global [%0],[%1],16;\n" :: "r"(d), "l"(g));
        }
#pragma unroll
        for (int i = 0; i < 2; i++) {            // B tile: 32x128 bf16
            int c = tid + i * 256;
            int r = c >> 4, cc = c & 15;
            uint32_t d = (uint32_t)__cvta_generic_to_shared(&sB[buf][r][cc * 8]);
            const __nv_bfloat16* g = &g_rhs_bf16[(size_t)(k0 + r) * NPAD + n0 + cc * 8];
            asm volatile("cp.async.cg.shared.global [%0],[%1],16;\n" :: "r"(d), "l"(g));
        }
    };

    auto compute = [&](int buf) {
#pragma unroll
        for (int ks = 0; ks < BK; ks += 16) {
            uint32_t af[2][4];
#pragma unroll
            for (int mi = 0; mi < 2; mi++) {
                uint32_t a = (uint32_t)__cvta_generic_to_shared(
                    &sA[buf][wm * 32 + mi * 16 + (lane & 15)][ks + (lane >> 4) * 8]);
                asm volatile("ldmatrix.sync.aligned.m8n8.x4.shared.b16 {%0,%1,%2,%3},[%4];"
                             : "=r"(af[mi][0]), "=r"(af[mi][1]), "=r"(af[mi][2]), "=r"(af[mi][3])
                             : "r"(a));
            }
            uint32_t bf[8][2];
#pragma unroll
            for (int nj = 0; nj < 4; nj++) {
                uint32_t a = (uint32_t)__cvta_generic_to_shared(
                    &sB[buf][ks + (lane & 15)][wn * 64 + nj * 16 + (lane >> 4) * 8]);
                uint32_t r0, r1, r2, r3;
                asm volatile("ldmatrix.sync.aligned.m8n8.x4.trans.shared.b16 {%0,%1,%2,%3},[%4];"
                             : "=r"(r0), "=r"(r1), "=r"(r2), "=r"(r3) : "r"(a));
                bf[nj * 2][0] = r0; bf[nj * 2][1] = r1;
                bf[nj * 2 + 1][0] = r2; bf[nj * 2 + 1][1] = r3;
            }
#pragma unroll
            for (int mi = 0; mi < 2; mi++)
#pragma unroll
                for (int ni = 0; ni < 8; ni++)
                    asm volatile("mma.sync.aligned.m16n8k16.row.col.f32.bf16.bf16.f32 "
                                 "{%0,%1,%2,%3},{%4,%5,%6,%7},{%8,%9},{%0,%1,%2,%3};"
                                 : "+f"(acc[mi][ni][0]), "+f"(acc[mi][ni][1]),
                                   "+f"(acc[mi][ni][2]), "+f"(acc[mi][ni][3])
                                 : "r"(af[mi][0]), "r"(af[mi][1]), "r"(af[mi][2]), "r"(af[mi][3]),
                                   "r"(bf[ni][0]), "r"(bf[ni][1]));
        }
    };

    load_stage(0, 0);
    asm volatile("cp.async.commit_group;\n");
    for (int kt = 0; kt < KT; kt++) {
        if (kt + 1 < KT) {
            load_stage(kt + 1, (kt + 1) & 1);
            asm volatile("cp.async.commit_group;\n");
            asm volatile("cp.async.wait_group 1;\n");
        } else {
            asm volatile("cp.async.wait_group 0;\n");
        }
        __syncthreads();
        compute(kt & 1);
        __syncthreads();
    }

    // ---- counting epilogue: compare to target, exclude masked + pad cols ----
    const int m_base = m0 + wm * 32;
    const int n_base = n0 + wn * 64;              // 64-aligned
    const int r_in = lane >> 2;
    const int c_in = (lane & 3) * 2;
    const int wbase = n_base >> 5;

#pragma unroll
    for (int mi = 0; mi < 2; mi++) {
        int r0 = m_base + mi * 16 + r_in;
        int r1 = r0 + 8;
        float t0 = g_targets[r0], t1 = g_targets[r1];
        unsigned w00 = g_mask[(size_t)r0 * NW + wbase];
        unsigned w01 = g_mask[(size_t)r0 * NW + wbase + 1];
        unsigned w10 = g_mask[(size_t)r1 * NW + wbase];
        unsigned w11 = g_mask[(size_t)r1 * NW + wbase + 1];
        int c0 = 0, c1 = 0;
#pragma unroll
        for (int ni = 0; ni < 8; ni++) {
#pragma unroll
            for (int e = 0; e < 2; e++) {
                int p = ni * 8 + c_in + e;
                bool v = (n_base + p) < N_COLS;
                unsigned mw0 = (p < 32) ? w00 : w01;
                unsigned mw1 = (p < 32) ? w10 : w11;
                if (v && !((mw0 >> (p & 31)) & 1u) && acc[mi][ni][e]     >= t0) c0++;
                if (v && !((mw1 >> (p & 31)) & 1u) && acc[mi][ni][2 + e] >= t1) c1++;
            }
        }
        c0 += __shfl_xor_sync(0xffffffffu, c0, 1);
        c0 += __shfl_xor_sync(0xffffffffu, c0, 2);
        c1 += __shfl_xor_sync(0xffffffffu, c1, 1);
        c1 += __shfl_xor_sync(0xffffffffu, c1, 2);
        if ((lane & 3) == 0) {
            atomicAdd(&g_counts[r0], c0);
            atomicAdd(&g_counts[r1], c1);
        }
    }
}

// ---------------- finalize ----------------
__global__ void k_final(float* __restrict__ out) {
    int i = blockIdx.x * 256 + threadIdx.x;
    if (i < B_ROWS) out[i] = 1.0f + (float)g_counts[i];
}

// ---------------- launch ----------------
extern "C" void kernel_launch(void* const* d_in, const int* in_sizes, int n_in,
                              void* d_out, int out_size) {
    const float* q   = (const float*)d_in[0];
    const float* rhs = (const float*)d_in[1];
    const void*  queries = d_in[2];
    const void*  filt    = d_in[3];
    float* out = (float*)d_out;

    k_detect<<<1, 256>>>((const unsigned*)queries);
    k_prep_rhs<<<(D_DIM * NPAD) / 256, 256>>>(rhs);
    k_prep_q<<<(B_ROWS * D_DIM) / 256, 256>>>(q);
    k_mask_zero<<<(B_ROWS * NW) / 256, 256>>>();
    k_mask_fill<<<(B_ROWS * 65 + 255) / 256, 256>>>(queries, filt);
    k_targets<<<B_ROWS / 8, 256>>>(q, rhs, queries);
    k_gemm<<<dim3(BM ? (B_ROWS / BM) : 1, NPAD / BN), 256>>>();
    k_final<<<(B_ROWS + 255) / 256, 256>>>(out);
}